// round 3
// baseline (speedup 1.0000x reference)
#include <cuda_runtime.h>
#include <math.h>

#define BATCH 64
#define SEQ   512
#define HID   1024
#define G3    3072
#define KDIM  1024

// ---------------- scratch (static device arrays; no allocations) ----------------
__device__ float g_gi[(size_t)SEQ * BATCH * G3];     // [t][b][3H]  (402 MB)
__device__ float g_hseq[(size_t)SEQ * BATCH * HID];  // [t][b][H]   (134 MB)
__device__ unsigned g_bar;

__global__ void zero_bar_kernel() { g_bar = 0u; }

// ---------------- GEMM:  GI[m][n] = Xrow(m) . W[n,:] + bias[n] ----------------
// m = t*64 + b ; Xrow addr = X + b*strideB + t*strideT ; W is [3072,1024] row-major.
#define BM 128
#define BN 128
#define BK 8

__global__ __launch_bounds__(256, 2)
void gemm_gi_kernel(const float* __restrict__ Xext, int fromHseq,
                    const float* __restrict__ W, const float* __restrict__ bias,
                    int strideB, int strideT)
{
    __shared__ float As[BK][BM];
    __shared__ float Bs[BK][BN];

    const float* X = fromHseq ? (const float*)g_hseq : Xext;

    int tid  = threadIdx.x;
    int mblk = blockIdx.x * BM;
    int nblk = blockIdx.y * BN;

    int lr  = tid >> 1;          // 0..127 tile row
    int lk4 = (tid & 1) * 4;     // 0 or 4

    int am = mblk + lr;
    int tt = am >> 6;            // / 64
    int bb = am & 63;
    const float* arow = X + (size_t)bb * strideB + (size_t)tt * strideT;
    const float* brow = W + (size_t)(nblk + lr) * KDIM;

    int tx = tid & 15, ty = tid >> 4;
    int m0 = ty * 8, n0 = tx * 8;

    float acc[8][8];
#pragma unroll
    for (int i = 0; i < 8; i++)
#pragma unroll
        for (int j = 0; j < 8; j++) acc[i][j] = 0.f;

    float4 av = *(const float4*)(arow + lk4);
    float4 bv = *(const float4*)(brow + lk4);

    for (int k0 = 0; k0 < KDIM; k0 += BK) {
        __syncthreads();
        As[lk4 + 0][lr] = av.x; As[lk4 + 1][lr] = av.y;
        As[lk4 + 2][lr] = av.z; As[lk4 + 3][lr] = av.w;
        Bs[lk4 + 0][lr] = bv.x; Bs[lk4 + 1][lr] = bv.y;
        Bs[lk4 + 2][lr] = bv.z; Bs[lk4 + 3][lr] = bv.w;
        __syncthreads();

        if (k0 + BK < KDIM) {
            av = *(const float4*)(arow + k0 + BK + lk4);
            bv = *(const float4*)(brow + k0 + BK + lk4);
        }

#pragma unroll
        for (int kk = 0; kk < BK; kk++) {
            float a[8], b[8];
            *(float4*)&a[0] = *(const float4*)&As[kk][m0];
            *(float4*)&a[4] = *(const float4*)&As[kk][m0 + 4];
            *(float4*)&b[0] = *(const float4*)&Bs[kk][n0];
            *(float4*)&b[4] = *(const float4*)&Bs[kk][n0 + 4];
#pragma unroll
            for (int i = 0; i < 8; i++)
#pragma unroll
                for (int j = 0; j < 8; j++)
                    acc[i][j] = fmaf(a[i], b[j], acc[i][j]);
        }
    }

    float bsv[8];
#pragma unroll
    for (int j = 0; j < 8; j++) bsv[j] = bias[nblk + n0 + j];

#pragma unroll
    for (int i = 0; i < 8; i++) {
        int m = mblk + m0 + i;
        float* orow = g_gi + (size_t)m * G3 + nblk + n0;
#pragma unroll
        for (int j = 0; j < 8; j++) orow[j] = acc[i][j] + bsv[j];
    }
}

// ---------------- persistent GRU recurrence (one layer, 512 steps) ----------------
// 128 CTAs x 128 threads. CTA owns 8 h-columns (j0..j0+7); its 24 w_hh rows
// (r,z,n for each j) live in smem for the whole kernel. Grid barrier per step.
#define RJ    8
#define RCTAS 128
#define RTH   128
#define KC    64
#define REC_SMEM_FLOATS (24 * 1024 + 64 * 65 + 24 * 65)
#define REC_SMEM_BYTES  (REC_SMEM_FLOATS * 4)

__global__ void gru_rec_kernel(const float* __restrict__ Whh, const float* __restrict__ bhh)
{
    extern __shared__ float sm[];
    float* Ws  = sm;                 // [24][1024]   weights (gate*8 + jj major)
    float* hs  = Ws + 24 * 1024;     // [KC][65]     staged h chunk, k-major, pitch 65
    float* ghs = hs + 64 * 65;       // [24][65]     gh exchange

    int tid = threadIdx.x;
    int j0  = blockIdx.x * RJ;

    // weight load (once per launch)
    for (int idx = tid; idx < 24 * 1024; idx += RTH) {
        int r = idx >> 10, k = idx & 1023;
        int gate = r >> 3, jj = r & 7;
        Ws[idx] = Whh[(size_t)(gate * HID + j0 + jj) * KDIM + k];
    }
    __syncthreads();

    int bq = tid & 15, rg = tid >> 4;   // 16 b-quads x 8 row-groups
    int b0 = bq * 4,  r0 = rg * 3;      // 4 batches x 3 rows per thread

    for (int t = 0; t < SEQ; t++) {
        float acc[4][3];
#pragma unroll
        for (int i = 0; i < 4; i++)
#pragma unroll
            for (int j = 0; j < 3; j++) acc[i][j] = 0.f;

        if (t > 0) {
            const float* hprev = g_hseq + (size_t)(t - 1) * BATCH * HID;
            float4 rbuf[8];
#pragma unroll
            for (int u = 0; u < 8; u++) {
                int idx = tid + u * RTH;
                int b = idx >> 4, k4 = (idx & 15) << 2;
                rbuf[u] = *(const float4*)(hprev + (size_t)b * HID + k4);
            }
            for (int c = 0; c < KDIM / KC; c++) {
                __syncthreads();
#pragma unroll
                for (int u = 0; u < 8; u++) {
                    int idx = tid + u * RTH;
                    int b = idx >> 4, k4 = (idx & 15) << 2;
                    hs[(k4 + 0) * 65 + b] = rbuf[u].x;
                    hs[(k4 + 1) * 65 + b] = rbuf[u].y;
                    hs[(k4 + 2) * 65 + b] = rbuf[u].z;
                    hs[(k4 + 3) * 65 + b] = rbuf[u].w;
                }
                __syncthreads();
                if (c + 1 < KDIM / KC) {
                    int kc0n = (c + 1) * KC;
#pragma unroll
                    for (int u = 0; u < 8; u++) {
                        int idx = tid + u * RTH;
                        int b = idx >> 4, k4 = (idx & 15) << 2;
                        rbuf[u] = *(const float4*)(hprev + (size_t)b * HID + kc0n + k4);
                    }
                }
                int kc0 = c * KC;
#pragma unroll 4
                for (int kk = 0; kk < KC; kk += 4) {
                    float4 w0 = *(const float4*)&Ws[(r0 + 0) * KDIM + kc0 + kk];
                    float4 w1 = *(const float4*)&Ws[(r0 + 1) * KDIM + kc0 + kk];
                    float4 w2 = *(const float4*)&Ws[(r0 + 2) * KDIM + kc0 + kk];
#pragma unroll
                    for (int i = 0; i < 4; i++) {
                        float h0 = hs[(kk + 0) * 65 + b0 + i];
                        float h1 = hs[(kk + 1) * 65 + b0 + i];
                        float h2 = hs[(kk + 2) * 65 + b0 + i];
                        float h3 = hs[(kk + 3) * 65 + b0 + i];
                        acc[i][0] = fmaf(h0, w0.x, fmaf(h1, w0.y, fmaf(h2, w0.z, fmaf(h3, w0.w, acc[i][0]))));
                        acc[i][1] = fmaf(h0, w1.x, fmaf(h1, w1.y, fmaf(h2, w1.z, fmaf(h3, w1.w, acc[i][1]))));
                        acc[i][2] = fmaf(h0, w2.x, fmaf(h1, w2.y, fmaf(h2, w2.z, fmaf(h3, w2.w, acc[i][2]))));
                    }
                }
            }
        }

        // exchange gh through smem
#pragma unroll
        for (int j = 0; j < 3; j++)
#pragma unroll
            for (int i = 0; i < 4; i++)
                ghs[(r0 + j) * 65 + b0 + i] = acc[i][j];
        __syncthreads();

        // gate math + h update (512 outputs per CTA, 4 per thread)
        const float* gi_t   = g_gi + (size_t)t * BATCH * G3;
        const float* hprev2 = g_hseq + (size_t)(t - 1) * BATCH * HID;
        float*       hout   = g_hseq + (size_t)t * BATCH * HID;
#pragma unroll
        for (int q = 0; q < 4; q++) {
            int idx = tid + q * RTH;     // 0..511
            int jj = idx & 7, b = idx >> 3;
            float ghr = ghs[(jj     ) * 65 + b] + bhh[            j0 + jj];
            float ghz = ghs[( 8 + jj) * 65 + b] + bhh[    HID  + j0 + jj];
            float ghn = ghs[(16 + jj) * 65 + b] + bhh[2 * HID  + j0 + jj];
            const float* gib = gi_t + (size_t)b * G3 + j0 + jj;
            float rr = 1.f / (1.f + expf(-(gib[0]        + ghr)));
            float zz = 1.f / (1.f + expf(-(gib[HID]      + ghz)));
            float nn = tanhf(gib[2 * HID] + rr * ghn);
            float hp = (t > 0) ? hprev2[(size_t)b * HID + j0 + jj] : 0.f;
            hout[(size_t)b * HID + j0 + jj] = (1.f - zz) * nn + zz * hp;
        }

        // grid barrier: every thread fences its stores, then thread0 arrives+spins
        __threadfence();
        __syncthreads();
        if (tid == 0) {
            unsigned tgt = (unsigned)(t + 1) * (unsigned)gridDim.x;
            atomicAdd(&g_bar, 1u);
            while (*((volatile unsigned*)&g_bar) < tgt) { __nanosleep(64); }
        }
        __syncthreads();
    }
}

// ---------------- final copy: layer-1 h at t = S-1 -> d_out [B,H] ----------------
__global__ void copy_out_kernel(float* __restrict__ out)
{
    int i = blockIdx.x * blockDim.x + threadIdx.x;
    out[i] = g_hseq[(size_t)(SEQ - 1) * BATCH * HID + i];
}

// ---------------- launch ----------------
extern "C" void kernel_launch(void* const* d_in, const int* in_sizes, int n_in,
                              void* d_out, int out_size)
{
    const float* x   = (const float*)d_in[0];
    const float* wih = (const float*)d_in[1];  // [2][3072][1024]
    const float* whh = (const float*)d_in[2];  // [2][3072][1024]
    const float* bih = (const float*)d_in[3];  // [2][3072]
    const float* bhh = (const float*)d_in[4];  // [2][3072]
    float* out = (float*)d_out;

    cudaFuncSetAttribute(gru_rec_kernel,
                         cudaFuncAttributeMaxDynamicSharedMemorySize, REC_SMEM_BYTES);

    dim3 gg((SEQ * BATCH) / BM, G3 / BN);      // (256, 24)
    const size_t LW = (size_t)G3 * KDIM;       // per-layer weight stride

    // layer 0
    zero_bar_kernel<<<1, 1>>>();
    gemm_gi_kernel<<<gg, 256>>>(x, 0, wih, bih, SEQ * KDIM, KDIM);
    gru_rec_kernel<<<RCTAS, RTH, REC_SMEM_BYTES>>>(whh, bhh);

    // layer 1 (input = layer-0 hidden sequence)
    zero_bar_kernel<<<1, 1>>>();
    gemm_gi_kernel<<<gg, 256>>>(x, 1, wih + LW, bih + G3, HID, BATCH * HID);
    gru_rec_kernel<<<RCTAS, RTH, REC_SMEM_BYTES>>>(whh + LW, bhh + G3);

    copy_out_kernel<<<(BATCH * HID) / 256, 256>>>(out);
}

// round 4
// speedup vs baseline: 1.9557x; 1.9557x over previous
#include <cuda_runtime.h>
#include <math.h>

#define BATCH 64
#define SEQ   512
#define HID   1024
#define G3    3072
#define KDIM  1024

typedef unsigned long long ull;

// packed fp32x2 FMA: d = a*b + d  (per 32-bit lane)
#define FMA2(d, a, b) \
    asm("fma.rn.f32x2 %0, %1, %2, %3;" : "=l"(d) : "l"(a), "l"(b), "l"(d))
#define PACK2(d, f) \
    asm("mov.b64 %0, {%1, %1};" : "=l"(d) : "f"(f))
#define UNPACK2(lo, hi, v) \
    asm("mov.b64 {%0, %1}, %2;" : "=f"(lo), "=f"(hi) : "l"(v))

// ---------------- scratch (static device arrays; no allocations) ----------------
__device__ float g_gi[(size_t)SEQ * BATCH * G3];     // [t][b][3H]
__device__ float g_hseq[(size_t)SEQ * BATCH * HID];  // [t][b][H]
__device__ unsigned g_bar;

__global__ void zero_bar_kernel() { g_bar = 0u; }

// ---------------- GEMM:  GI[m][n] = Xrow(m) . W[n,:] + bias[n] ----------------
// grid (24, 256): x = n-block (keeps W hot in L2 while m streams), y = m-block.
#define BM 128
#define BN 128
#define BK 8

__global__ __launch_bounds__(128, 2)
void gemm_gi_kernel(const float* __restrict__ Xext, int fromHseq,
                    const float* __restrict__ W, const float* __restrict__ bias,
                    int strideB, int strideT)
{
    __shared__ float As[BK][BM];
    __shared__ float Bs[BK][BN];

    const float* X = fromHseq ? (const float*)g_hseq : Xext;

    int tid  = threadIdx.x;
    int nblk = blockIdx.x * BN;
    int mblk = blockIdx.y * BM;

    // each thread owns one row of the A tile and one row of the B tile (8 k each)
    int am = mblk + tid;
    int tt = am >> 6;
    int bb = am & 63;
    const float* arow = X + (size_t)bb * strideB + (size_t)tt * strideT;
    const float* brow = W + (size_t)(nblk + tid) * KDIM;

    int tx = tid & 15, ty = tid >> 4;
    int m0 = tx * 8, n0 = ty * 16;

    ull acc[4][16];
#pragma unroll
    for (int p = 0; p < 4; p++)
#pragma unroll
        for (int j = 0; j < 16; j++) acc[p][j] = 0ull;

    float4 av0 = *(const float4*)(arow + 0);
    float4 av1 = *(const float4*)(arow + 4);
    float4 bv0 = *(const float4*)(brow + 0);
    float4 bv1 = *(const float4*)(brow + 4);

    for (int k0 = 0; k0 < KDIM; k0 += BK) {
        __syncthreads();
        As[0][tid] = av0.x; As[1][tid] = av0.y; As[2][tid] = av0.z; As[3][tid] = av0.w;
        As[4][tid] = av1.x; As[5][tid] = av1.y; As[6][tid] = av1.z; As[7][tid] = av1.w;
        Bs[0][tid] = bv0.x; Bs[1][tid] = bv0.y; Bs[2][tid] = bv0.z; Bs[3][tid] = bv0.w;
        Bs[4][tid] = bv1.x; Bs[5][tid] = bv1.y; Bs[6][tid] = bv1.z; Bs[7][tid] = bv1.w;
        __syncthreads();

        if (k0 + BK < KDIM) {
            av0 = *(const float4*)(arow + k0 + BK + 0);
            av1 = *(const float4*)(arow + k0 + BK + 4);
            bv0 = *(const float4*)(brow + k0 + BK + 0);
            bv1 = *(const float4*)(brow + k0 + BK + 4);
        }

#pragma unroll
        for (int kk = 0; kk < BK; kk++) {
            // a: 4 m-pairs (contiguous, 16B-aligned)
            ulonglong2 a01 = *(const ulonglong2*)&As[kk][m0];
            ulonglong2 a23 = *(const ulonglong2*)&As[kk][m0 + 4];
            ull ap[4] = {a01.x, a01.y, a23.x, a23.y};
            // b: 16 scalars, replicated into both f32x2 lanes
            float4 b0 = *(const float4*)&Bs[kk][n0];
            float4 b1 = *(const float4*)&Bs[kk][n0 + 4];
            float4 b2 = *(const float4*)&Bs[kk][n0 + 8];
            float4 b3 = *(const float4*)&Bs[kk][n0 + 12];
            float bf[16] = {b0.x,b0.y,b0.z,b0.w, b1.x,b1.y,b1.z,b1.w,
                            b2.x,b2.y,b2.z,b2.w, b3.x,b3.y,b3.z,b3.w};
            ull bp[16];
#pragma unroll
            for (int j = 0; j < 16; j++) PACK2(bp[j], bf[j]);
#pragma unroll
            for (int p = 0; p < 4; p++)
#pragma unroll
                for (int j = 0; j < 16; j++)
                    FMA2(acc[p][j], ap[p], bp[j]);
        }
    }

    float bsv[16];
#pragma unroll
    for (int j = 0; j < 16; j++) bsv[j] = bias[nblk + n0 + j];

#pragma unroll
    for (int p = 0; p < 4; p++) {
        float lo[16], hi[16];
#pragma unroll
        for (int j = 0; j < 16; j++) UNPACK2(lo[j], hi[j], acc[p][j]);
        float* r0 = g_gi + (size_t)(mblk + m0 + 2 * p)     * G3 + nblk + n0;
        float* r1 = g_gi + (size_t)(mblk + m0 + 2 * p + 1) * G3 + nblk + n0;
#pragma unroll
        for (int j = 0; j < 16; j++) { r0[j] = lo[j] + bsv[j]; r1[j] = hi[j] + bsv[j]; }
    }
}

// ---------------- persistent GRU recurrence (one layer, 512 steps) ----------------
// 128 CTAs x 256 threads. CTA owns 8 h-columns; 24 w_hh rows live in smem.
// f32x2 packed over k-pairs; thread tile = 6 rows x 8 batches; k split 8 ways.
#define RJ    8
#define RCTAS 128
#define RTH   256
#define KC    64
#define NCH   (KDIM / KC)          // 16
#define WSP   1032                 // Ws row pitch (floats): conflict-free lane spread
#define KP    68                   // hs batch pitch (floats): 272B, 16B-aligned
#define REC_SMEM_FLOATS (24 * WSP + 2 * 64 * KP + 24 * 65)
#define REC_SMEM_BYTES  (REC_SMEM_FLOATS * 4)

__global__ __launch_bounds__(RTH, 1)
void gru_rec_kernel(const float* __restrict__ Whh, const float* __restrict__ bhh)
{
    extern __shared__ float sm[];
    float* Ws    = sm;                       // [24][WSP]
    float* hsbuf = Ws + 24 * WSP;            // 2 x [64][KP]  h chunk, b-major
    float* ghs   = hsbuf + 2 * 64 * KP;      // [24][65]      gh exchange

    int tid = threadIdx.x;
    int j0  = blockIdx.x * RJ;

    // weight load (once per launch); row r = gate*8 + jj
    for (int idx = tid; idx < 24 * 1024; idx += RTH) {
        int r = idx >> 10, k = idx & 1023;
        int gate = r >> 3, jj = r & 7;
        Ws[r * WSP + k] = Whh[(size_t)(gate * HID + j0 + jj) * KDIM + k];
    }
    __syncthreads();

    int s  = tid & 7;            // k-split lane (stride-16 interleaved pairs)
    int rg = (tid >> 3) & 3;     // row group (6 rows each)
    int bg = tid >> 5;           // batch group == warp id (8 batches each)
    int r0 = rg * 6;
    int b0 = bg * 8;

    for (int t = 0; t < SEQ; t++) {
        ull acc[6][8];
#pragma unroll
        for (int j = 0; j < 6; j++)
#pragma unroll
            for (int b = 0; b < 8; b++) acc[j][b] = 0ull;

        if (t > 0) {
            const float* hprev = g_hseq + (size_t)(t - 1) * BATCH * HID;

            // stage chunk 0 into buffer 0
            int fb = tid >> 4;            // batch (0..63): 16 float4 per batch row? no:
            int fk = tid & 15;            // 4096 floats = 1024 float4; thread u-loop below
            float4 pf[4];
#pragma unroll
            for (int u = 0; u < 4; u++) {
                int fid = tid + u * RTH;            // 0..1023
                int b = fid >> 4, k4 = fid & 15;
                pf[u] = *(const float4*)(hprev + (size_t)b * HID + k4 * 4);
            }
#pragma unroll
            for (int u = 0; u < 4; u++) {
                int fid = tid + u * RTH;
                int b = fid >> 4, k4 = fid & 15;
                *(float4*)&hsbuf[b * KP + k4 * 4] = pf[u];
            }
            __syncthreads();

            for (int c = 0; c < NCH; c++) {
                // prefetch next chunk (global) while computing this one
                if (c + 1 < NCH) {
                    int kb = (c + 1) * KC;
#pragma unroll
                    for (int u = 0; u < 4; u++) {
                        int fid = tid + u * RTH;
                        int b = fid >> 4, k4 = fid & 15;
                        pf[u] = *(const float4*)(hprev + (size_t)b * HID + kb + k4 * 4);
                    }
                }

                const float* hsb = hsbuf + (c & 1) * 64 * KP;
                int kabs = c * KC + 2 * s;
                int kloc = 2 * s;
#pragma unroll
                for (int i = 0; i < 4; i++) {
                    ull w[6], h[8];
#pragma unroll
                    for (int j = 0; j < 6; j++)
                        w[j] = *(const ull*)&Ws[(r0 + j) * WSP + kabs + 16 * i];
#pragma unroll
                    for (int b = 0; b < 8; b++)
                        h[b] = *(const ull*)&hsb[(b0 + b) * KP + kloc + 16 * i];
#pragma unroll
                    for (int j = 0; j < 6; j++)
#pragma unroll
                        for (int b = 0; b < 8; b++)
                            FMA2(acc[j][b], w[j], h[b]);
                }

                if (c + 1 < NCH) {
                    float* dst = hsbuf + ((c + 1) & 1) * 64 * KP;
#pragma unroll
                    for (int u = 0; u < 4; u++) {
                        int fid = tid + u * RTH;
                        int b = fid >> 4, k4 = fid & 15;
                        *(float4*)&dst[b * KP + k4 * 4] = pf[u];
                    }
                }
                __syncthreads();
            }
        }

        // reduce: horizontal f32x2 add, then shfl over the 8 k-split lanes
#pragma unroll
        for (int j = 0; j < 6; j++) {
#pragma unroll
            for (int b = 0; b < 8; b++) {
                float lo, hi;
                UNPACK2(lo, hi, acc[j][b]);
                float v = lo + hi;
                v += __shfl_xor_sync(0xffffffffu, v, 1);
                v += __shfl_xor_sync(0xffffffffu, v, 2);
                v += __shfl_xor_sync(0xffffffffu, v, 4);
                if (s == 0) ghs[(r0 + j) * 65 + b0 + b] = v;
            }
        }
        __syncthreads();

        // gate math + h update (512 outputs per CTA, 2 per thread)
        const float* gi_t   = g_gi + (size_t)t * BATCH * G3;
        const float* hprev2 = g_hseq + (size_t)(t - 1) * BATCH * HID;
        float*       hout   = g_hseq + (size_t)t * BATCH * HID;
#pragma unroll
        for (int q = 0; q < 2; q++) {
            int idx = tid + q * RTH;     // 0..511
            int jj = idx & 7, b = idx >> 3;
            float ghr = ghs[(jj     ) * 65 + b] + bhh[           j0 + jj];
            float ghz = ghs[( 8 + jj) * 65 + b] + bhh[    HID  + j0 + jj];
            float ghn = ghs[(16 + jj) * 65 + b] + bhh[2 * HID  + j0 + jj];
            const float* gib = gi_t + (size_t)b * G3 + j0 + jj;
            float rr = 1.f / (1.f + expf(-(gib[0]        + ghr)));
            float zz = 1.f / (1.f + expf(-(gib[HID]      + ghz)));
            float nn = tanhf(gib[2 * HID] + rr * ghn);
            float hp = (t > 0) ? hprev2[(size_t)b * HID + j0 + jj] : 0.f;
            hout[(size_t)b * HID + j0 + jj] = (1.f - zz) * nn + zz * hp;
        }

        // grid barrier
        __threadfence();
        __syncthreads();
        if (tid == 0) {
            unsigned tgt = (unsigned)(t + 1) * (unsigned)gridDim.x;
            atomicAdd(&g_bar, 1u);
            while (*((volatile unsigned*)&g_bar) < tgt) { __nanosleep(64); }
        }
        __syncthreads();
    }
}

// ---------------- final copy: layer-1 h at t = S-1 -> d_out [B,H] ----------------
__global__ void copy_out_kernel(float* __restrict__ out)
{
    int i = blockIdx.x * blockDim.x + threadIdx.x;
    out[i] = g_hseq[(size_t)(SEQ - 1) * BATCH * HID + i];
}

// ---------------- launch ----------------
extern "C" void kernel_launch(void* const* d_in, const int* in_sizes, int n_in,
                              void* d_out, int out_size)
{
    const float* x   = (const float*)d_in[0];
    const float* wih = (const float*)d_in[1];  // [2][3072][1024]
    const float* whh = (const float*)d_in[2];  // [2][3072][1024]
    const float* bih = (const float*)d_in[3];  // [2][3072]
    const float* bhh = (const float*)d_in[4];  // [2][3072]
    float* out = (float*)d_out;

    cudaFuncSetAttribute(gru_rec_kernel,
                         cudaFuncAttributeMaxDynamicSharedMemorySize, REC_SMEM_BYTES);

    dim3 gg(G3 / BN, (SEQ * BATCH) / BM);      // (24, 256): n fast, m slow
    const size_t LW = (size_t)G3 * KDIM;       // per-layer weight stride

    // layer 0
    zero_bar_kernel<<<1, 1>>>();
    gemm_gi_kernel<<<gg, 128>>>(x, 0, wih, bih, SEQ * KDIM, KDIM);
    gru_rec_kernel<<<RCTAS, RTH, REC_SMEM_BYTES>>>(whh, bhh);

    // layer 1 (input = layer-0 hidden sequence)
    zero_bar_kernel<<<1, 1>>>();
    gemm_gi_kernel<<<gg, 128>>>(x, 1, wih + LW, bih + G3, HID, BATCH * HID);
    gru_rec_kernel<<<RCTAS, RTH, REC_SMEM_BYTES>>>(whh + LW, bhh + G3);

    copy_out_kernel<<<(BATCH * HID) / 256, 256>>>(out);
}